// round 10
// baseline (speedup 1.0000x reference)
#include <cuda_runtime.h>
#include <cuda_fp16.h>
#include <cstdint>

#define NROWS 8192
#define DIM   512
#define BM    128
#define BN    128
#define BK    64
#define STAGES 3
#define KCHUNKS (DIM / BK)        // 8

// Scratch (allocation-free rule: __device__ globals)
__device__ __half g_sb[(size_t)NROWS * DIM];
__device__ __half g_tb[(size_t)NROWS * DIM];
__device__ float g_ssq[NROWS];
__device__ float g_tsq[NROWS];

__device__ __forceinline__ uint32_t smem_u32(const void* p) {
    return (uint32_t)__cvta_generic_to_shared(p);
}
#define SW128(o) ((o) ^ ((((uint32_t)(o)) >> 3) & 0x70u))

__device__ __forceinline__ void cp_async16(uint32_t smem_addr, const void* gptr) {
    asm volatile("cp.async.cg.shared.global [%0], [%1], 16;" :: "r"(smem_addr), "l"(gptr));
}
__device__ __forceinline__ void cp_commit() {
    asm volatile("cp.async.commit_group;" ::: "memory");
}
template <int N>
__device__ __forceinline__ void cp_wait() {
    asm volatile("cp.async.wait_group %0;" :: "n"(N) : "memory");
}

__device__ __forceinline__ void ldmatrix_x4(uint32_t& r0, uint32_t& r1, uint32_t& r2, uint32_t& r3,
                                            uint32_t addr) {
    asm volatile("ldmatrix.sync.aligned.m8n8.x4.shared.b16 {%0,%1,%2,%3}, [%4];"
                 : "=r"(r0), "=r"(r1), "=r"(r2), "=r"(r3) : "r"(addr));
}

// fp16 HMMA with fp16 accumulate: D(f16) = A(f16)*B(f16) + C(f16)
// C/D are 2 x b32 regs (4 halves): reg0 = {row r: col c0, c1}, reg1 = {row r+8: c0, c1}
__device__ __forceinline__ void mma_16816_f16acc(uint32_t* c, const uint32_t* a,
                                                 uint32_t b0, uint32_t b1) {
    asm volatile(
        "mma.sync.aligned.m16n8k16.row.col.f16.f16.f16.f16 "
        "{%0,%1}, {%2,%3,%4,%5}, {%6,%7}, {%0,%1};"
        : "+r"(c[0]), "+r"(c[1])
        : "r"(a[0]), "r"(a[1]), "r"(a[2]), "r"(a[3]), "r"(b0), "r"(b1));
}

// ---------------------------------------------------------------------------
// Kernel 1: fp32 -> fp16 conversion + row square-norms (fp32-exact)
// ---------------------------------------------------------------------------
__global__ __launch_bounds__(128) void convert_kernel(const float* __restrict__ s,
                                                      const float* __restrict__ t) {
    int row = blockIdx.x;
    const float* src;
    __half* dst;
    float* sqout;
    if (row < NROWS) {
        src = s + (size_t)row * DIM;
        dst = g_sb + (size_t)row * DIM;
        sqout = g_ssq + row;
    } else {
        int r = row - NROWS;
        src = t + (size_t)r * DIM;
        dst = g_tb + (size_t)r * DIM;
        sqout = g_tsq + r;
    }
    int tid = threadIdx.x;  // 0..127, DIM/4 = 128 float4 per row
    float4 v = reinterpret_cast<const float4*>(src)[tid];
    float acc = v.x * v.x + v.y * v.y + v.z * v.z + v.w * v.w;

    __half2 lo = __floats2half2_rn(v.x, v.y);
    __half2 hi = __floats2half2_rn(v.z, v.w);
    reinterpret_cast<__half2*>(dst)[2 * tid]     = lo;
    reinterpret_cast<__half2*>(dst)[2 * tid + 1] = hi;

    #pragma unroll
    for (int o = 16; o > 0; o >>= 1) acc += __shfl_xor_sync(0xFFFFFFFFu, acc, o);
    __shared__ float partial[4];
    if ((tid & 31) == 0) partial[tid >> 5] = acc;
    __syncthreads();
    if (tid == 0) *sqout = partial[0] + partial[1] + partial[2] + partial[3];
}

// ---------------------------------------------------------------------------
// Kernel 2: fp16 HMMA GEMM (f16 accumulate) + fused distance epilogue
// CTA tile 128x128x64, 256 threads (8 warps, 2m x 4n, warp tile 64x32),
// 3-stage cp.async pipeline, ONE __syncthreads per K-chunk, 2 CTAs/SM.
// ---------------------------------------------------------------------------
#define A_STAGE_BYTES (BM * 128)                       // 16 KB
#define B_STAGE_BYTES (BN * 128)                       // 16 KB
#define STAGE_BYTES   (A_STAGE_BYTES + B_STAGE_BYTES)  // 32 KB

extern __shared__ __align__(1024) char dyn_smem[];

__global__ __launch_bounds__(256, 2) void dist_kernel(float* __restrict__ out) {
    const int tid  = threadIdx.x;
    const int wid  = tid >> 5;
    const int lane = tid & 31;
    const int warp_m = wid >> 2;       // 0..1 (64-row slabs)
    const int warp_n = wid & 3;        // 0..3 (32-col slabs)
    const int m0 = blockIdx.y * BM;
    const int n0 = blockIdx.x * BN;

    // tsq staged in smem (tail of the dynamic allocation)
    float* s_tsq = reinterpret_cast<float*>(dyn_smem + STAGES * STAGE_BYTES);
    if (tid < BN) s_tsq[tid] = g_tsq[n0 + tid];

    const int cm  = tid >> 3;          // cp.async base row (0..31; i adds 32 rows)
    const int ck8 = tid & 7;           // 16B column within the 128B row
    const __half* ga = g_sb + (size_t)(m0 + cm) * DIM + ck8 * 8;
    const __half* gb = g_tb + (size_t)(n0 + cm) * DIM + ck8 * 8;
    const uint32_t smem_base = smem_u32(dyn_smem);

    uint32_t acc[4][4][2];             // f16x2 accumulators
    #pragma unroll
    for (int mi = 0; mi < 4; mi++)
        #pragma unroll
        for (int ni = 0; ni < 4; ni++) { acc[mi][ni][0] = 0u; acc[mi][ni][1] = 0u; }

    const uint32_t a_row  = (uint32_t)(warp_m * 64 + (lane & 15));
    const uint32_t a_colh = (uint32_t)((lane >> 4) * 16);
    const uint32_t b_row  = (uint32_t)(warp_n * 32 + (lane & 7) + ((lane & 16) ? 8 : 0));
    const uint32_t b_colh = (uint32_t)(((lane >> 3) & 1) * 16);

    // Prologue: stages 0..1 load K-chunks 0..1 (2 committed groups)
    #pragma unroll
    for (int st = 0; st < 2; st++) {
        const uint32_t abase = smem_base + st * STAGE_BYTES;
        const uint32_t bbase = abase + A_STAGE_BYTES;
        #pragma unroll
        for (int i = 0; i < 4; i++) {
            const uint32_t so = SW128(((uint32_t)(cm + i * 32)) * 128u + (uint32_t)ck8 * 16u);
            cp_async16(abase + so, ga + (size_t)(i * 32) * DIM + st * BK);
            cp_async16(bbase + so, gb + (size_t)(i * 32) * DIM + st * BK);
        }
        cp_commit();
    }

    for (int kc = 0; kc < KCHUNKS; kc++) {
        cp_wait<1>();        // chunk kc resident; kc+1 may remain in flight
        __syncthreads();     // certifies all warps finished reading chunk kc-1

        // Issue chunk kc+2 into stage (kc+2)%3 == stage of chunk kc-1 (now free).
        const int knext = kc + 2;
        if (knext < KCHUNKS) {
            const uint32_t abase_n = smem_base + (knext % STAGES) * STAGE_BYTES;
            const uint32_t bbase_n = abase_n + A_STAGE_BYTES;
            #pragma unroll
            for (int i = 0; i < 4; i++) {
                const uint32_t so = SW128(((uint32_t)(cm + i * 32)) * 128u + (uint32_t)ck8 * 16u);
                cp_async16(abase_n + so, ga + (size_t)(i * 32) * DIM + knext * BK);
                cp_async16(bbase_n + so, gb + (size_t)(i * 32) * DIM + knext * BK);
            }
        }
        cp_commit();         // empty groups in the tail keep wait<1> counting exact

        const uint32_t abase = smem_base + (kc % STAGES) * STAGE_BYTES;
        const uint32_t bbase = abase + A_STAGE_BYTES;

        #pragma unroll
        for (int ks = 0; ks < 4; ks++) {
            uint32_t af[4][4];
            uint32_t bf[2][4];
            #pragma unroll
            for (int mi = 0; mi < 4; mi++) {
                const uint32_t off = (a_row + mi * 16) * 128u + (uint32_t)(ks * 32) + a_colh;
                ldmatrix_x4(af[mi][0], af[mi][1], af[mi][2], af[mi][3], abase + SW128(off));
            }
            #pragma unroll
            for (int g = 0; g < 2; g++) {
                const uint32_t off = (b_row + g * 16) * 128u + (uint32_t)(ks * 32) + b_colh;
                ldmatrix_x4(bf[g][0], bf[g][1], bf[g][2], bf[g][3], bbase + SW128(off));
            }
            #pragma unroll
            for (int mi = 0; mi < 4; mi++) {
                #pragma unroll
                for (int ni = 0; ni < 4; ni++) {
                    const int g = ni >> 1, p = ni & 1;
                    mma_16816_f16acc(acc[mi][ni], af[mi], bf[g][p * 2], bf[g][p * 2 + 1]);
                }
            }
        }
    }

    // ---------------- Epilogue: dist = ssq + tsq - 2*cross ----------------
    const int groupID = lane >> 2;
    const int tig = lane & 3;
    #pragma unroll
    for (int mi = 0; mi < 4; mi++) {
        const int row0 = m0 + warp_m * 64 + mi * 16 + groupID;
        const int row1 = row0 + 8;
        const float sq0 = g_ssq[row0];
        const float sq1 = g_ssq[row1];
        float* o0 = out + (size_t)row0 * NROWS;
        float* o1 = out + (size_t)row1 * NROWS;
        #pragma unroll
        for (int ni = 0; ni < 4; ni++) {
            const int lc = warp_n * 32 + ni * 8 + tig * 2;    // local col in tile
            const int col = n0 + lc;
            const float tq0 = s_tsq[lc];
            const float tq1 = s_tsq[lc + 1];
            const __half2 c01 = *reinterpret_cast<const __half2*>(&acc[mi][ni][0]);
            const __half2 c23 = *reinterpret_cast<const __half2*>(&acc[mi][ni][1]);
            float2 v0, v1;
            v0.x = sq0 + tq0 - 2.0f * __half2float(__low2half(c01));
            v0.y = sq0 + tq1 - 2.0f * __half2float(__high2half(c01));
            v1.x = sq1 + tq0 - 2.0f * __half2float(__low2half(c23));
            v1.y = sq1 + tq1 - 2.0f * __half2float(__high2half(c23));
            *reinterpret_cast<float2*>(o0 + col) = v0;
            *reinterpret_cast<float2*>(o1 + col) = v1;
        }
    }
}

// ---------------------------------------------------------------------------
extern "C" void kernel_launch(void* const* d_in, const int* in_sizes, int n_in,
                              void* d_out, int out_size) {
    const float* s = (const float*)d_in[0];
    const float* t = (const float*)d_in[1];
    float* out = (float*)d_out;

    const int smem_bytes = STAGES * STAGE_BYTES + BN * (int)sizeof(float);
    cudaFuncSetAttribute(dist_kernel, cudaFuncAttributeMaxDynamicSharedMemorySize,
                         smem_bytes);

    convert_kernel<<<2 * NROWS, 128>>>(s, t);
    dim3 grid(NROWS / BN, NROWS / BM);
    dist_kernel<<<grid, 256, smem_bytes>>>(out);
}

// round 11
// speedup vs baseline: 1.0293x; 1.0293x over previous
#include <cuda_runtime.h>
#include <cuda_bf16.h>
#include <cstdint>

#define NROWS 8192
#define DIM   512
#define BM    128
#define BN    128
#define BK    64
#define STAGES 3
#define KCHUNKS (DIM / BK)        // 8

// Scratch (allocation-free rule: __device__ globals)
__device__ __nv_bfloat16 g_sb[(size_t)NROWS * DIM];
__device__ __nv_bfloat16 g_tb[(size_t)NROWS * DIM];
__device__ float g_ssq[NROWS];
__device__ float g_tsq[NROWS];

__device__ __forceinline__ uint32_t smem_u32(const void* p) {
    return (uint32_t)__cvta_generic_to_shared(p);
}
#define SW128(o) ((o) ^ ((((uint32_t)(o)) >> 3) & 0x70u))

__device__ __forceinline__ void cp_async16(uint32_t smem_addr, const void* gptr) {
    asm volatile("cp.async.cg.shared.global [%0], [%1], 16;" :: "r"(smem_addr), "l"(gptr));
}
__device__ __forceinline__ void cp_commit() {
    asm volatile("cp.async.commit_group;" ::: "memory");
}
template <int N>
__device__ __forceinline__ void cp_wait() {
    asm volatile("cp.async.wait_group %0;" :: "n"(N) : "memory");
}

__device__ __forceinline__ void ldmatrix_x4(uint32_t& r0, uint32_t& r1, uint32_t& r2, uint32_t& r3,
                                            uint32_t addr) {
    asm volatile("ldmatrix.sync.aligned.m8n8.x4.shared.b16 {%0,%1,%2,%3}, [%4];"
                 : "=r"(r0), "=r"(r1), "=r"(r2), "=r"(r3) : "r"(addr));
}

__device__ __forceinline__ void mma_16816(float* c, const uint32_t* a, uint32_t b0, uint32_t b1) {
    asm volatile(
        "mma.sync.aligned.m16n8k16.row.col.f32.bf16.bf16.f32 "
        "{%0,%1,%2,%3}, {%4,%5,%6,%7}, {%8,%9}, {%0,%1,%2,%3};"
        : "+f"(c[0]), "+f"(c[1]), "+f"(c[2]), "+f"(c[3])
        : "r"(a[0]), "r"(a[1]), "r"(a[2]), "r"(a[3]), "r"(b0), "r"(b1));
}

// Streaming fp32x2 store (write-once output; don't pollute L2)
__device__ __forceinline__ void stg_cs_f2(float* p, float x, float y) {
    asm volatile("st.global.cs.v2.f32 [%0], {%1, %2};" :: "l"(p), "f"(x), "f"(y) : "memory");
}

// ---------------------------------------------------------------------------
// Kernel 1: fp32 -> bf16 conversion + row square-norms (fp32-exact).
// 256 threads/block, 2 rows per block (one row per 128-thread half).
// Blocks [0, NROWS) handle s (2 rows each); [NROWS, 2*NROWS) handle t.
// ---------------------------------------------------------------------------
__global__ __launch_bounds__(256) void convert_kernel(const float* __restrict__ s,
                                                      const float* __restrict__ t) {
    const int half = threadIdx.x >> 7;            // 0 or 1: which row of the pair
    const int tid  = threadIdx.x & 127;           // 0..127 within the row
    int row2 = blockIdx.x * 2 + half;
    const float* src;
    __nv_bfloat16* dst;
    float* sqout;
    if (row2 < 2 * NROWS ? (blockIdx.x < NROWS / 2) : false) { /* never */ }
    if (blockIdx.x < NROWS / 2) {
        src = s + (size_t)row2 * DIM;
        dst = g_sb + (size_t)row2 * DIM;
        sqout = g_ssq + row2;
    } else {
        int r = row2 - NROWS;
        src = t + (size_t)r * DIM;
        dst = g_tb + (size_t)r * DIM;
        sqout = g_tsq + r;
    }
    float4 v = reinterpret_cast<const float4*>(src)[tid];
    float acc = v.x * v.x + v.y * v.y + v.z * v.z + v.w * v.w;

    __nv_bfloat162 lo = __floats2bfloat162_rn(v.x, v.y);
    __nv_bfloat162 hi = __floats2bfloat162_rn(v.z, v.w);
    reinterpret_cast<__nv_bfloat162*>(dst)[2 * tid]     = lo;
    reinterpret_cast<__nv_bfloat162*>(dst)[2 * tid + 1] = hi;

    #pragma unroll
    for (int o = 16; o > 0; o >>= 1) acc += __shfl_xor_sync(0xFFFFFFFFu, acc, o);
    __shared__ float partial[8];
    if ((tid & 31) == 0) partial[threadIdx.x >> 5] = acc;
    __syncthreads();
    if (tid == 0) {
        const int b = half * 4;
        *sqout = partial[b] + partial[b + 1] + partial[b + 2] + partial[b + 3];
    }
}

// ---------------------------------------------------------------------------
// Kernel 2: bf16 HMMA GEMM + fused distance epilogue
// CTA tile 128x128x64, 256 threads (8 warps, 2m x 4n, warp tile 64x32),
// 3-stage cp.async pipeline, ONE __syncthreads per K-chunk, 2 CTAs/SM.
// ---------------------------------------------------------------------------
#define A_STAGE_BYTES (BM * 128)                       // 16 KB
#define B_STAGE_BYTES (BN * 128)                       // 16 KB
#define STAGE_BYTES   (A_STAGE_BYTES + B_STAGE_BYTES)  // 32 KB

extern __shared__ __align__(1024) char dyn_smem[];

__global__ __launch_bounds__(256, 2) void dist_kernel(float* __restrict__ out) {
    const int tid  = threadIdx.x;
    const int wid  = tid >> 5;
    const int lane = tid & 31;
    const int warp_m = wid >> 2;       // 0..1 (64-row slabs)
    const int warp_n = wid & 3;        // 0..3 (32-col slabs)
    const int m0 = blockIdx.y * BM;
    const int n0 = blockIdx.x * BN;

    // tsq staged in smem (tail of the dynamic allocation)
    float* s_tsq = reinterpret_cast<float*>(dyn_smem + STAGES * STAGE_BYTES);
    if (tid < BN) s_tsq[tid] = g_tsq[n0 + tid];

    const int cm  = tid >> 3;          // cp.async base row (0..31; i adds 32 rows)
    const int ck8 = tid & 7;           // 16B column within the 128B row
    const __nv_bfloat16* ga = g_sb + (size_t)(m0 + cm) * DIM + ck8 * 8;
    const __nv_bfloat16* gb = g_tb + (size_t)(n0 + cm) * DIM + ck8 * 8;
    const uint32_t smem_base = smem_u32(dyn_smem);

    float acc[4][4][4];
    #pragma unroll
    for (int mi = 0; mi < 4; mi++)
        #pragma unroll
        for (int ni = 0; ni < 4; ni++)
            #pragma unroll
            for (int k = 0; k < 4; k++) acc[mi][ni][k] = 0.0f;

    const uint32_t a_row  = (uint32_t)(warp_m * 64 + (lane & 15));
    const uint32_t a_colh = (uint32_t)((lane >> 4) * 16);
    const uint32_t b_row  = (uint32_t)(warp_n * 32 + (lane & 7) + ((lane & 16) ? 8 : 0));
    const uint32_t b_colh = (uint32_t)(((lane >> 3) & 1) * 16);

    // Prologue: stages 0..1 load K-chunks 0..1 (2 committed groups)
    #pragma unroll
    for (int st = 0; st < 2; st++) {
        const uint32_t abase = smem_base + st * STAGE_BYTES;
        const uint32_t bbase = abase + A_STAGE_BYTES;
        #pragma unroll
        for (int i = 0; i < 4; i++) {
            const uint32_t so = SW128(((uint32_t)(cm + i * 32)) * 128u + (uint32_t)ck8 * 16u);
            cp_async16(abase + so, ga + (size_t)(i * 32) * DIM + st * BK);
            cp_async16(bbase + so, gb + (size_t)(i * 32) * DIM + st * BK);
        }
        cp_commit();
    }

    for (int kc = 0; kc < KCHUNKS; kc++) {
        cp_wait<1>();        // chunk kc resident; kc+1 may remain in flight
        __syncthreads();     // certifies all warps finished reading chunk kc-1

        // Issue chunk kc+2 into stage (kc+2)%3 == stage of chunk kc-1 (now free).
        const int knext = kc + 2;
        if (knext < KCHUNKS) {
            const uint32_t abase_n = smem_base + (knext % STAGES) * STAGE_BYTES;
            const uint32_t bbase_n = abase_n + A_STAGE_BYTES;
            #pragma unroll
            for (int i = 0; i < 4; i++) {
                const uint32_t so = SW128(((uint32_t)(cm + i * 32)) * 128u + (uint32_t)ck8 * 16u);
                cp_async16(abase_n + so, ga + (size_t)(i * 32) * DIM + knext * BK);
                cp_async16(bbase_n + so, gb + (size_t)(i * 32) * DIM + knext * BK);
            }
        }
        cp_commit();         // empty groups in the tail keep wait<1> counting exact

        const uint32_t abase = smem_base + (kc % STAGES) * STAGE_BYTES;
        const uint32_t bbase = abase + A_STAGE_BYTES;

        #pragma unroll
        for (int ks = 0; ks < 4; ks++) {
            uint32_t af[4][4];
            uint32_t bf[2][4];
            #pragma unroll
            for (int mi = 0; mi < 4; mi++) {
                const uint32_t off = (a_row + mi * 16) * 128u + (uint32_t)(ks * 32) + a_colh;
                ldmatrix_x4(af[mi][0], af[mi][1], af[mi][2], af[mi][3], abase + SW128(off));
            }
            #pragma unroll
            for (int g = 0; g < 2; g++) {
                const uint32_t off = (b_row + g * 16) * 128u + (uint32_t)(ks * 32) + b_colh;
                ldmatrix_x4(bf[g][0], bf[g][1], bf[g][2], bf[g][3], bbase + SW128(off));
            }
            #pragma unroll
            for (int mi = 0; mi < 4; mi++) {
                #pragma unroll
                for (int ni = 0; ni < 4; ni++) {
                    const int g = ni >> 1, p = ni & 1;
                    mma_16816(acc[mi][ni], af[mi], bf[g][p * 2], bf[g][p * 2 + 1]);
                }
            }
        }
    }

    // ---------------- Epilogue: dist = ssq + tsq - 2*cross ----------------
    const int groupID = lane >> 2;
    const int tig = lane & 3;
    #pragma unroll
    for (int mi = 0; mi < 4; mi++) {
        const int row0 = m0 + warp_m * 64 + mi * 16 + groupID;
        const int row1 = row0 + 8;
        const float sq0 = g_ssq[row0];
        const float sq1 = g_ssq[row1];
        float* o0 = out + (size_t)row0 * NROWS;
        float* o1 = out + (size_t)row1 * NROWS;
        #pragma unroll
        for (int ni = 0; ni < 4; ni++) {
            const int lc = warp_n * 32 + ni * 8 + tig * 2;    // local col in tile
            const int col = n0 + lc;
            const float tq0 = s_tsq[lc];
            const float tq1 = s_tsq[lc + 1];
            stg_cs_f2(o0 + col, sq0 + tq0 - 2.0f * acc[mi][ni][0],
                                sq0 + tq1 - 2.0f * acc[mi][ni][1]);
            stg_cs_f2(o1 + col, sq1 + tq0 - 2.0f * acc[mi][ni][2],
                                sq1 + tq1 - 2.0f * acc[mi][ni][3]);
        }
    }
}

// ---------------------------------------------------------------------------
extern "C" void kernel_launch(void* const* d_in, const int* in_sizes, int n_in,
                              void* d_out, int out_size) {
    const float* s = (const float*)d_in[0];
    const float* t = (const float*)d_in[1];
    float* out = (float*)d_out;

    const int smem_bytes = STAGES * STAGE_BYTES + BN * (int)sizeof(float);
    cudaFuncSetAttribute(dist_kernel, cudaFuncAttributeMaxDynamicSharedMemorySize,
                         smem_bytes);

    convert_kernel<<<NROWS, 256>>>(s, t);   // NROWS blocks: first half -> s rows, second -> t
    dim3 grid(NROWS / BN, NROWS / BM);
    dist_kernel<<<grid, 256, smem_bytes>>>(out);
}

// round 12
// speedup vs baseline: 1.0381x; 1.0086x over previous
#include <cuda_runtime.h>
#include <cuda_bf16.h>
#include <cstdint>

#define NROWS 8192
#define DIM   512
#define BM    128
#define BN    128
#define BK    64
#define STAGES 3
#define KCHUNKS (DIM / BK)        // 8

// Scratch (allocation-free rule: __device__ globals)
__device__ __nv_bfloat16 g_sb[(size_t)NROWS * DIM];
__device__ __nv_bfloat16 g_tb[(size_t)NROWS * DIM];
__device__ float g_ssq[NROWS];
__device__ float g_tsq[NROWS];

__device__ __forceinline__ uint32_t smem_u32(const void* p) {
    return (uint32_t)__cvta_generic_to_shared(p);
}
#define SW128(o) ((o) ^ ((((uint32_t)(o)) >> 3) & 0x70u))

__device__ __forceinline__ void cp_async16(uint32_t smem_addr, const void* gptr) {
    asm volatile("cp.async.cg.shared.global [%0], [%1], 16;" :: "r"(smem_addr), "l"(gptr));
}
__device__ __forceinline__ void cp_commit() {
    asm volatile("cp.async.commit_group;" ::: "memory");
}
template <int N>
__device__ __forceinline__ void cp_wait() {
    asm volatile("cp.async.wait_group %0;" :: "n"(N) : "memory");
}

__device__ __forceinline__ void ldmatrix_x4(uint32_t& r0, uint32_t& r1, uint32_t& r2, uint32_t& r3,
                                            uint32_t addr) {
    asm volatile("ldmatrix.sync.aligned.m8n8.x4.shared.b16 {%0,%1,%2,%3}, [%4];"
                 : "=r"(r0), "=r"(r1), "=r"(r2), "=r"(r3) : "r"(addr));
}

__device__ __forceinline__ void mma_16816(float* c, const uint32_t* a, uint32_t b0, uint32_t b1) {
    asm volatile(
        "mma.sync.aligned.m16n8k16.row.col.f32.bf16.bf16.f32 "
        "{%0,%1,%2,%3}, {%4,%5,%6,%7}, {%8,%9}, {%0,%1,%2,%3};"
        : "+f"(c[0]), "+f"(c[1]), "+f"(c[2]), "+f"(c[3])
        : "r"(a[0]), "r"(a[1]), "r"(a[2]), "r"(a[3]), "r"(b0), "r"(b1));
}

// Streaming fp32x2 store (write-once output; don't pollute L2)
__device__ __forceinline__ void stg_cs_f2(float* p, float x, float y) {
    asm volatile("st.global.cs.v2.f32 [%0], {%1, %2};" :: "l"(p), "f"(x), "f"(y) : "memory");
}

// ---------------------------------------------------------------------------
// Kernel 1: fp32 -> bf16 conversion + row square-norms (fp32-exact).
// Warp-per-row: each warp owns one full row (DIM=512 -> 4 float4 per lane).
// No __syncthreads, warp-shuffle reduction only. 256 threads = 8 rows/block.
// Rows [0, NROWS) are s; [NROWS, 2*NROWS) are t.
// ---------------------------------------------------------------------------
__global__ __launch_bounds__(256) void convert_kernel(const float* __restrict__ s,
                                                      const float* __restrict__ t) {
    const int wid  = threadIdx.x >> 5;
    const int lane = threadIdx.x & 31;
    const int row  = blockIdx.x * 8 + wid;

    const float* src;
    __nv_bfloat16* dst;
    float* sqout;
    if (row < NROWS) {
        src = s + (size_t)row * DIM;
        dst = g_sb + (size_t)row * DIM;
        sqout = g_ssq + row;
    } else {
        const int r = row - NROWS;
        src = t + (size_t)r * DIM;
        dst = g_tb + (size_t)r * DIM;
        sqout = g_tsq + r;
    }

    const float4* src4 = reinterpret_cast<const float4*>(src);
    __nv_bfloat162* dst2 = reinterpret_cast<__nv_bfloat162*>(dst);

    float acc = 0.0f;
    #pragma unroll
    for (int j = 0; j < 4; j++) {
        const int idx = lane + 32 * j;              // float4 index 0..127
        float4 v = src4[idx];
        acc += v.x * v.x + v.y * v.y + v.z * v.z + v.w * v.w;
        dst2[2 * idx]     = __floats2bfloat162_rn(v.x, v.y);
        dst2[2 * idx + 1] = __floats2bfloat162_rn(v.z, v.w);
    }

    #pragma unroll
    for (int o = 16; o > 0; o >>= 1) acc += __shfl_xor_sync(0xFFFFFFFFu, acc, o);
    if (lane == 0) *sqout = acc;
}

// ---------------------------------------------------------------------------
// Kernel 2: bf16 HMMA GEMM + fused distance epilogue
// CTA tile 128x128x64, 256 threads (8 warps, 2m x 4n, warp tile 64x32),
// 3-stage cp.async pipeline, ONE __syncthreads per K-chunk, 2 CTAs/SM.
// ssq and tsq for the tile staged in smem at kernel start.
// ---------------------------------------------------------------------------
#define A_STAGE_BYTES (BM * 128)                       // 16 KB
#define B_STAGE_BYTES (BN * 128)                       // 16 KB
#define STAGE_BYTES   (A_STAGE_BYTES + B_STAGE_BYTES)  // 32 KB

extern __shared__ __align__(1024) char dyn_smem[];

__global__ __launch_bounds__(256, 2) void dist_kernel(float* __restrict__ out) {
    const int tid  = threadIdx.x;
    const int wid  = tid >> 5;
    const int lane = tid & 31;
    const int warp_m = wid >> 2;       // 0..1 (64-row slabs)
    const int warp_n = wid & 3;        // 0..3 (32-col slabs)
    const int m0 = blockIdx.y * BM;
    const int n0 = blockIdx.x * BN;

    // tsq + ssq staged in smem (tail of the dynamic allocation)
    float* s_tsq = reinterpret_cast<float*>(dyn_smem + STAGES * STAGE_BYTES);
    float* s_ssq = s_tsq + BN;
    if (tid < BN) {
        s_tsq[tid] = g_tsq[n0 + tid];
        s_ssq[tid] = g_ssq[m0 + tid];   // BM == BN == 128
    }

    const int cm  = tid >> 3;          // cp.async base row (0..31; i adds 32 rows)
    const int ck8 = tid & 7;           // 16B column within the 128B row
    const __nv_bfloat16* ga = g_sb + (size_t)(m0 + cm) * DIM + ck8 * 8;
    const __nv_bfloat16* gb = g_tb + (size_t)(n0 + cm) * DIM + ck8 * 8;
    const uint32_t smem_base = smem_u32(dyn_smem);

    float acc[4][4][4];
    #pragma unroll
    for (int mi = 0; mi < 4; mi++)
        #pragma unroll
        for (int ni = 0; ni < 4; ni++)
            #pragma unroll
            for (int k = 0; k < 4; k++) acc[mi][ni][k] = 0.0f;

    const uint32_t a_row  = (uint32_t)(warp_m * 64 + (lane & 15));
    const uint32_t a_colh = (uint32_t)((lane >> 4) * 16);
    const uint32_t b_row  = (uint32_t)(warp_n * 32 + (lane & 7) + ((lane & 16) ? 8 : 0));
    const uint32_t b_colh = (uint32_t)(((lane >> 3) & 1) * 16);

    // Prologue: stages 0..1 load K-chunks 0..1 (2 committed groups)
    #pragma unroll
    for (int st = 0; st < 2; st++) {
        const uint32_t abase = smem_base + st * STAGE_BYTES;
        const uint32_t bbase = abase + A_STAGE_BYTES;
        #pragma unroll
        for (int i = 0; i < 4; i++) {
            const uint32_t so = SW128(((uint32_t)(cm + i * 32)) * 128u + (uint32_t)ck8 * 16u);
            cp_async16(abase + so, ga + (size_t)(i * 32) * DIM + st * BK);
            cp_async16(bbase + so, gb + (size_t)(i * 32) * DIM + st * BK);
        }
        cp_commit();
    }

    for (int kc = 0; kc < KCHUNKS; kc++) {
        cp_wait<1>();        // chunk kc resident; kc+1 may remain in flight
        __syncthreads();     // certifies all warps finished reading chunk kc-1

        // Issue chunk kc+2 into stage (kc+2)%3 == stage of chunk kc-1 (now free).
        const int knext = kc + 2;
        if (knext < KCHUNKS) {
            const uint32_t abase_n = smem_base + (knext % STAGES) * STAGE_BYTES;
            const uint32_t bbase_n = abase_n + A_STAGE_BYTES;
            #pragma unroll
            for (int i = 0; i < 4; i++) {
                const uint32_t so = SW128(((uint32_t)(cm + i * 32)) * 128u + (uint32_t)ck8 * 16u);
                cp_async16(abase_n + so, ga + (size_t)(i * 32) * DIM + knext * BK);
                cp_async16(bbase_n + so, gb + (size_t)(i * 32) * DIM + knext * BK);
            }
        }
        cp_commit();         // empty groups in the tail keep wait<1> counting exact

        const uint32_t abase = smem_base + (kc % STAGES) * STAGE_BYTES;
        const uint32_t bbase = abase + A_STAGE_BYTES;

        #pragma unroll
        for (int ks = 0; ks < 4; ks++) {
            uint32_t af[4][4];
            uint32_t bf[2][4];
            #pragma unroll
            for (int mi = 0; mi < 4; mi++) {
                const uint32_t off = (a_row + mi * 16) * 128u + (uint32_t)(ks * 32) + a_colh;
                ldmatrix_x4(af[mi][0], af[mi][1], af[mi][2], af[mi][3], abase + SW128(off));
            }
            #pragma unroll
            for (int g = 0; g < 2; g++) {
                const uint32_t off = (b_row + g * 16) * 128u + (uint32_t)(ks * 32) + b_colh;
                ldmatrix_x4(bf[g][0], bf[g][1], bf[g][2], bf[g][3], bbase + SW128(off));
            }
            #pragma unroll
            for (int mi = 0; mi < 4; mi++) {
                #pragma unroll
                for (int ni = 0; ni < 4; ni++) {
                    const int g = ni >> 1, p = ni & 1;
                    mma_16816(acc[mi][ni], af[mi], bf[g][p * 2], bf[g][p * 2 + 1]);
                }
            }
        }
    }

    // ---------------- Epilogue: dist = ssq + tsq - 2*cross ----------------
    const int groupID = lane >> 2;
    const int tig = lane & 3;
    #pragma unroll
    for (int mi = 0; mi < 4; mi++) {
        const int lr0 = warp_m * 64 + mi * 16 + groupID;   // local row in tile
        const int row0 = m0 + lr0;
        const int row1 = row0 + 8;
        const float sq0 = s_ssq[lr0];
        const float sq1 = s_ssq[lr0 + 8];
        float* o0 = out + (size_t)row0 * NROWS;
        float* o1 = out + (size_t)row1 * NROWS;
        #pragma unroll
        for (int ni = 0; ni < 4; ni++) {
            const int lc = warp_n * 32 + ni * 8 + tig * 2;    // local col in tile
            const int col = n0 + lc;
            const float tq0 = s_tsq[lc];
            const float tq1 = s_tsq[lc + 1];
            stg_cs_f2(o0 + col, sq0 + tq0 - 2.0f * acc[mi][ni][0],
                                sq0 + tq1 - 2.0f * acc[mi][ni][1]);
            stg_cs_f2(o1 + col, sq1 + tq0 - 2.0f * acc[mi][ni][2],
                                sq1 + tq1 - 2.0f * acc[mi][ni][3]);
        }
    }
}

// ---------------------------------------------------------------------------
extern "C" void kernel_launch(void* const* d_in, const int* in_sizes, int n_in,
                              void* d_out, int out_size) {
    const float* s = (const float*)d_in[0];
    const float* t = (const float*)d_in[1];
    float* out = (float*)d_out;

    const int smem_bytes = STAGES * STAGE_BYTES + (BN + BM) * (int)sizeof(float);
    cudaFuncSetAttribute(dist_kernel, cudaFuncAttributeMaxDynamicSharedMemorySize,
                         smem_bytes);

    convert_kernel<<<2 * NROWS / 8, 256>>>(s, t);
    dim3 grid(NROWS / BN, NROWS / BM);
    dist_kernel<<<grid, 256, smem_bytes>>>(out);
}

// round 13
// speedup vs baseline: 1.0494x; 1.0109x over previous
#include <cuda_runtime.h>
#include <cuda_bf16.h>
#include <cstdint>

#define NROWS 8192
#define DIM   512
#define BM    128
#define BN    128
#define BK    64
#define STAGES 3
#define KCHUNKS (DIM / BK)        // 8

// Scratch (allocation-free rule: __device__ globals)
__device__ __nv_bfloat16 g_sb[(size_t)NROWS * DIM];
__device__ __nv_bfloat16 g_tb[(size_t)NROWS * DIM];
__device__ float g_ssq[NROWS];
__device__ float g_tsq[NROWS];

__device__ __forceinline__ uint32_t smem_u32(const void* p) {
    return (uint32_t)__cvta_generic_to_shared(p);
}
#define SW128(o) ((o) ^ ((((uint32_t)(o)) >> 3) & 0x70u))

__device__ __forceinline__ void cp_async16(uint32_t smem_addr, const void* gptr) {
    asm volatile("cp.async.cg.shared.global [%0], [%1], 16;" :: "r"(smem_addr), "l"(gptr));
}
__device__ __forceinline__ void cp_commit() {
    asm volatile("cp.async.commit_group;" ::: "memory");
}
template <int N>
__device__ __forceinline__ void cp_wait() {
    asm volatile("cp.async.wait_group %0;" :: "n"(N) : "memory");
}

__device__ __forceinline__ void ldmatrix_x4(uint32_t& r0, uint32_t& r1, uint32_t& r2, uint32_t& r3,
                                            uint32_t addr) {
    asm volatile("ldmatrix.sync.aligned.m8n8.x4.shared.b16 {%0,%1,%2,%3}, [%4];"
                 : "=r"(r0), "=r"(r1), "=r"(r2), "=r"(r3) : "r"(addr));
}

__device__ __forceinline__ void mma_16816(float* c, const uint32_t* a, uint32_t b0, uint32_t b1) {
    asm volatile(
        "mma.sync.aligned.m16n8k16.row.col.f32.bf16.bf16.f32 "
        "{%0,%1,%2,%3}, {%4,%5,%6,%7}, {%8,%9}, {%0,%1,%2,%3};"
        : "+f"(c[0]), "+f"(c[1]), "+f"(c[2]), "+f"(c[3])
        : "r"(a[0]), "r"(a[1]), "r"(a[2]), "r"(a[3]), "r"(b0), "r"(b1));
}

// Streaming fp32x2 store (write-once output; don't pollute L2)
__device__ __forceinline__ void stg_cs_f2(float* p, float x, float y) {
    asm volatile("st.global.cs.v2.f32 [%0], {%1, %2};" :: "l"(p), "f"(x), "f"(y) : "memory");
}

// ---------------------------------------------------------------------------
// Kernel 1: fp32 -> bf16 conversion + row square-norms (fp32-exact).
// Warp-per-row: each warp owns one full row (DIM=512 -> 4 float4 per lane).
// No __syncthreads, warp-shuffle reduction only. 256 threads = 8 rows/block.
// Rows [0, NROWS) are s; [NROWS, 2*NROWS) are t.
// ---------------------------------------------------------------------------
__global__ __launch_bounds__(256) void convert_kernel(const float* __restrict__ s,
                                                      const float* __restrict__ t) {
    const int wid  = threadIdx.x >> 5;
    const int lane = threadIdx.x & 31;
    const int row  = blockIdx.x * 8 + wid;

    const float* src;
    __nv_bfloat16* dst;
    float* sqout;
    if (row < NROWS) {
        src = s + (size_t)row * DIM;
        dst = g_sb + (size_t)row * DIM;
        sqout = g_ssq + row;
    } else {
        const int r = row - NROWS;
        src = t + (size_t)r * DIM;
        dst = g_tb + (size_t)r * DIM;
        sqout = g_tsq + r;
    }

    const float4* src4 = reinterpret_cast<const float4*>(src);
    __nv_bfloat162* dst2 = reinterpret_cast<__nv_bfloat162*>(dst);

    float acc = 0.0f;
    #pragma unroll
    for (int j = 0; j < 4; j++) {
        const int idx = lane + 32 * j;              // float4 index 0..127
        float4 v = src4[idx];
        acc += v.x * v.x + v.y * v.y + v.z * v.z + v.w * v.w;
        dst2[2 * idx]     = __floats2bfloat162_rn(v.x, v.y);
        dst2[2 * idx + 1] = __floats2bfloat162_rn(v.z, v.w);
    }

    #pragma unroll
    for (int o = 16; o > 0; o >>= 1) acc += __shfl_xor_sync(0xFFFFFFFFu, acc, o);
    if (lane == 0) *sqout = acc;
}

// ---------------------------------------------------------------------------
// Kernel 2: bf16 HMMA GEMM + fused distance epilogue
// CTA tile 128x128x64, 256 threads (8 warps, 2m x 4n, warp tile 64x32),
// 3-stage cp.async pipeline, ONE __syncthreads per K-chunk, 2 CTAs/SM.
// ssq and tsq for the tile staged in smem at kernel start.
// Per-chunk: all 24 swizzled ldmatrix addresses precomputed once.
// ---------------------------------------------------------------------------
#define A_STAGE_BYTES (BM * 128)                       // 16 KB
#define B_STAGE_BYTES (BN * 128)                       // 16 KB
#define STAGE_BYTES   (A_STAGE_BYTES + B_STAGE_BYTES)  // 32 KB

extern __shared__ __align__(1024) char dyn_smem[];

__global__ __launch_bounds__(256, 2) void dist_kernel(float* __restrict__ out) {
    const int tid  = threadIdx.x;
    const int wid  = tid >> 5;
    const int lane = tid & 31;
    const int warp_m = wid >> 2;       // 0..1 (64-row slabs)
    const int warp_n = wid & 3;        // 0..3 (32-col slabs)
    const int m0 = blockIdx.y * BM;
    const int n0 = blockIdx.x * BN;

    // tsq + ssq staged in smem (tail of the dynamic allocation)
    float* s_tsq = reinterpret_cast<float*>(dyn_smem + STAGES * STAGE_BYTES);
    float* s_ssq = s_tsq + BN;
    if (tid < BN) {
        s_tsq[tid] = g_tsq[n0 + tid];
        s_ssq[tid] = g_ssq[m0 + tid];   // BM == BN == 128
    }

    const int cm  = tid >> 3;          // cp.async base row (0..31; i adds 32 rows)
    const int ck8 = tid & 7;           // 16B column within the 128B row
    const __nv_bfloat16* ga = g_sb + (size_t)(m0 + cm) * DIM + ck8 * 8;
    const __nv_bfloat16* gb = g_tb + (size_t)(n0 + cm) * DIM + ck8 * 8;
    const uint32_t smem_base = smem_u32(dyn_smem);

    float acc[4][4][4];
    #pragma unroll
    for (int mi = 0; mi < 4; mi++)
        #pragma unroll
        for (int ni = 0; ni < 4; ni++)
            #pragma unroll
            for (int k = 0; k < 4; k++) acc[mi][ni][k] = 0.0f;

    const uint32_t a_row  = (uint32_t)(warp_m * 64 + (lane & 15));
    const uint32_t a_colh = (uint32_t)((lane >> 4) * 16);
    const uint32_t b_row  = (uint32_t)(warp_n * 32 + (lane & 7) + ((lane & 16) ? 8 : 0));
    const uint32_t b_colh = (uint32_t)(((lane >> 3) & 1) * 16);

    // Per-fragment logical byte offsets within a stage buffer (swizzle applied
    // per-ks below; ks*32 touches swizzle input bits so it can't be hoisted out
    // of SW128, but these row*128 bases are loop-invariant).
    uint32_t a_off0[4], b_off0[2];
    #pragma unroll
    for (int mi = 0; mi < 4; mi++) a_off0[mi] = (a_row + mi * 16) * 128u + a_colh;
    #pragma unroll
    for (int g = 0; g < 2; g++)    b_off0[g]  = (b_row + g * 16) * 128u + b_colh;

    // Prologue: stages 0..1 load K-chunks 0..1 (2 committed groups)
    #pragma unroll
    for (int st = 0; st < 2; st++) {
        const uint32_t abase = smem_base + st * STAGE_BYTES;
        const uint32_t bbase = abase + A_STAGE_BYTES;
        #pragma unroll
        for (int i = 0; i < 4; i++) {
            const uint32_t so = SW128(((uint32_t)(cm + i * 32)) * 128u + (uint32_t)ck8 * 16u);
            cp_async16(abase + so, ga + (size_t)(i * 32) * DIM + st * BK);
            cp_async16(bbase + so, gb + (size_t)(i * 32) * DIM + st * BK);
        }
        cp_commit();
    }

    for (int kc = 0; kc < KCHUNKS; kc++) {
        cp_wait<1>();        // chunk kc resident; kc+1 may remain in flight
        __syncthreads();     // certifies all warps finished reading chunk kc-1

        // Issue chunk kc+2 into stage (kc+2)%3 == stage of chunk kc-1 (now free).
        const int knext = kc + 2;
        if (knext < KCHUNKS) {
            const uint32_t abase_n = smem_base + (knext % STAGES) * STAGE_BYTES;
            const uint32_t bbase_n = abase_n + A_STAGE_BYTES;
            #pragma unroll
            for (int i = 0; i < 4; i++) {
                const uint32_t so = SW128(((uint32_t)(cm + i * 32)) * 128u + (uint32_t)ck8 * 16u);
                cp_async16(abase_n + so, ga + (size_t)(i * 32) * DIM + knext * BK);
                cp_async16(bbase_n + so, gb + (size_t)(i * 32) * DIM + knext * BK);
            }
        }
        cp_commit();         // empty groups in the tail keep wait<1> counting exact

        const uint32_t abase = smem_base + (kc % STAGES) * STAGE_BYTES;
        const uint32_t bbase = abase + A_STAGE_BYTES;

        // Precompute all swizzled addresses for this chunk (24 values).
        uint32_t a_addr[4][4], b_addr[4][2];
        #pragma unroll
        for (int ks = 0; ks < 4; ks++) {
            const uint32_t kso = (uint32_t)(ks * 32);
            #pragma unroll
            for (int mi = 0; mi < 4; mi++) a_addr[ks][mi] = abase + SW128(a_off0[mi] + kso);
            #pragma unroll
            for (int g = 0; g < 2; g++)    b_addr[ks][g]  = bbase + SW128(b_off0[g] + kso);
        }

        #pragma unroll
        for (int ks = 0; ks < 4; ks++) {
            uint32_t af[4][4];
            uint32_t bf[2][4];
            #pragma unroll
            for (int mi = 0; mi < 4; mi++)
                ldmatrix_x4(af[mi][0], af[mi][1], af[mi][2], af[mi][3], a_addr[ks][mi]);
            #pragma unroll
            for (int g = 0; g < 2; g++)
                ldmatrix_x4(bf[g][0], bf[g][1], bf[g][2], bf[g][3], b_addr[ks][g]);
            #pragma unroll
            for (int mi = 0; mi < 4; mi++) {
                #pragma unroll
                for (int ni = 0; ni < 4; ni++) {
                    const int g = ni >> 1, p = ni & 1;
                    mma_16816(acc[mi][ni], af[mi], bf[g][p * 2], bf[g][p * 2 + 1]);
                }
            }
        }
    }

    // ---------------- Epilogue: dist = ssq + tsq - 2*cross ----------------
    const int groupID = lane >> 2;
    const int tig = lane & 3;
    #pragma unroll
    for (int mi = 0; mi < 4; mi++) {
        const int lr0 = warp_m * 64 + mi * 16 + groupID;   // local row in tile
        const int row0 = m0 + lr0;
        const int row1 = row0 + 8;
        const float sq0 = s_ssq[lr0];
        const float sq1 = s_ssq[lr0 + 8];
        float* o0 = out + (size_t)row0 * NROWS;
        float* o1 = out + (size_t)row1 * NROWS;
        #pragma unroll
        for (int ni = 0; ni < 4; ni++) {
            const int lc = warp_n * 32 + ni * 8 + tig * 2;    // local col in tile
            const int col = n0 + lc;
            const float tq0 = s_tsq[lc];
            const float tq1 = s_tsq[lc + 1];
            stg_cs_f2(o0 + col, sq0 + tq0 - 2.0f * acc[mi][ni][0],
                                sq0 + tq1 - 2.0f * acc[mi][ni][1]);
            stg_cs_f2(o1 + col, sq1 + tq0 - 2.0f * acc[mi][ni][2],
                                sq1 + tq1 - 2.0f * acc[mi][ni][3]);
        }
    }
}

// ---------------------------------------------------------------------------
extern "C" void kernel_launch(void* const* d_in, const int* in_sizes, int n_in,
                              void* d_out, int out_size) {
    const float* s = (const float*)d_in[0];
    const float* t = (const float*)d_in[1];
    float* out = (float*)d_out;

    const int smem_bytes = STAGES * STAGE_BYTES + (BN + BM) * (int)sizeof(float);
    cudaFuncSetAttribute(dist_kernel, cudaFuncAttributeMaxDynamicSharedMemorySize,
                         smem_bytes);

    convert_kernel<<<2 * NROWS / 8, 256>>>(s, t);
    dim3 grid(NROWS / BN, NROWS / BM);
    dist_kernel<<<grid, 256, smem_bytes>>>(out);
}